// round 11
// baseline (speedup 1.0000x reference)
#include <cuda_runtime.h>
#include <math.h>

#define IMG    256
#define PSZ    16
#define PAD    8
#define NBR    64
#define CH     3
#define INV2S2 12.5f
#define EPSV   1e-7f
#define PADP   20      // patchT row pitch [c][q][p]
#define PFX    28      // Fx row pitch [q][wl]
#define PFY    24      // Fy row pitch [p][hl]
#define PT     28      // tt row pitch [p][wl]
#define NBRUSH 2048
#define WPC    4                    // warps (=brushes) per CTA
#define GRID   (NBRUSH / WPC)       // 512
#define TOTW   NBRUSH               // total warps = arrivals

// per-slot smem (floats): patch 960 | fx 448 | fy 384 | tt 448
#define SLOT_F   2240
#define OFF_FX   960
#define OFF_FY   1408
#define OFF_TT   1792

__device__ unsigned int arrive_g;   // monotonic ticket counter (graph-replay safe)

__global__ __launch_bounds__(128) void brush_kernel(
    const float* __restrict__ brushes,   // [B, N, 2]
    const float* __restrict__ patches,   // [B, N, 3, 16, 16]
    float* __restrict__ out)             // [B, 3, 256, 256]
{
    extern __shared__ __align__(16) float dyn_s[];
    __shared__ float e_s[WPC][2][8];
    __shared__ float rden_s[WPC][2][16];

    const int tid  = threadIdx.x;
    const int w    = tid >> 5;           // slot / warp id
    const int lane = tid & 31;
    const int bn   = blockIdx.x * WPC + w;
    const int b    = bn >> 6;

    float* ws      = dyn_s + w * SLOT_F;
    float* patchT  = ws;                 // [c][q][p] pitch 20
    float* fxs     = ws + OFF_FX;        // [q][wl]
    float* fys     = ws + OFF_FY;        // [p][hl]
    float* tts     = ws + OFF_TT;        // [p][wl] (per-channel, reused)

    // ---- phase 0: zero this warp's 768-float4 slice; arrive on ticket ----
    {
        float4* o4 = (float4*)out + (size_t)bn * 768 + lane;
        const float4 z = make_float4(0.f, 0.f, 0.f, 0.f);
        #pragma unroll
        for (int k = 0; k < 24; k++) o4[k * 32] = z;
    }
    __threadfence();
    unsigned tgt = 0;
    if (lane == 0) {
        const unsigned ticket = atomicAdd(&arrive_g, 1u);
        tgt = (ticket / TOTW + 1u) * TOTW;
    }
    tgt = __shfl_sync(0xffffffffu, tgt, 0);

    // ---- phase 1: brush params (all lanes), exp table (lanes 0-15) ----
    const float gx = brushes[bn * 2 + 0] * (float)IMG;
    const float gy = brushes[bn * 2 + 1] * (float)IMG;
    const int flx = (int)floorf(gx), fly = (int)floorf(gy);
    const int t0x = flx - 10,        t0y = fly - 10;
    const int w0x = (flx - 11) & ~3, w0y = fly - 11;

    if (lane < 16) {
        const int ax = lane >> 3;
        const int k  = lane & 7;
        const float g  = ax ? gy : gx;
        const int   t0 = ax ? t0y : t0x;
        const float d  = (float)(t0 + k) - (g - 7.5f);
        e_s[w][ax][k] = __expf(-d * d * INV2S2);
    }
    __syncwarp();
    {   // reciprocal denominators: all 32 lanes (ax = lane>>4, q = lane&15)
        const int ax = lane >> 4;
        const int q  = lane & 15;
        const int t0 = ax ? t0y : t0x;
        int klo = -PAD - q - t0;            if (klo < 0) klo = 0;
        int khi = (IMG + PAD - 1) - q - t0; if (khi > 7) khi = 7;
        float s = 0.f;
        #pragma unroll
        for (int kk = 0; kk < 8; kk++)
            if (kk >= klo && kk <= khi) s += e_s[w][ax][kk];
        s += EPSV;
        rden_s[w][ax][q] = (ax == 0) ? 1.f / (s * (float)NBR) : 1.f / s;
    }

    // ---- phase 2: patch transpose load (768 elems, 24/lane) ----
    {
        const float* pbase = patches + (size_t)bn * (CH * PSZ * PSZ);
        #pragma unroll
        for (int j = 0; j < 24; j++) {
            const int i = lane + j * 32;
            const int c = i >> 8;
            const int p = (i >> 4) & 15;
            const int q = i & 15;
            patchT[(c * PSZ + q) * PADP + p] = pbase[i];
        }
    }
    __syncwarp();

    // ---- phase 3: filter fill via table lookups ----
    #pragma unroll
    for (int j = 0; j < 14; j++) {       // fx: 448 entries
        const int i  = lane + j * 32;
        const int q  = i / PFX;
        const int wl = i - q * PFX;
        const int ww = w0x + wl;
        const int idx = ww - q - t0x;
        float val = 0.f;
        if (ww >= 0 && ww < IMG && (unsigned)idx < 8u)
            val = e_s[w][0][idx] * rden_s[w][0][q];
        fxs[i] = val;
    }
    #pragma unroll
    for (int j = 0; j < 12; j++) {       // fy: 384 entries
        const int i  = lane + j * 32;
        const int p  = i / PFY;
        const int hl = i - p * PFY;
        const int hh = w0y + hl;
        const int idx = hh - p - t0y;
        float val = 0.f;
        if (hh >= 0 && hh < IMG && (unsigned)idx < 8u)
            val = e_s[w][1][idx] * rden_s[w][1][p];
        fys[i] = val;
    }
    __syncwarp();

    // ---- phase 4: per-channel stage1 -> stage2 ----
    float* base0 = out + (size_t)b * CH * (IMG * IMG);
    #pragma unroll
    for (int c = 0; c < CH; c++) {
        // stage 1: tt[p][wl] = sum_q fx[q][wl] * patchT[c][q][p]   (28 tasks)
        if (lane < 28) {
            const int wlq = lane % 7;
            const int pg  = lane / 7;
            const int p0  = pg * 4;
            const int wl0 = wlq * 4;
            const float* ptb = patchT + c * (PSZ * PADP);

            float acc[4][4] = {};   // [wl][p]
            #pragma unroll
            for (int q = 0; q < PSZ; q++) {
                const float4 fx = *(const float4*)&fxs[q * PFX + wl0];
                const float4 pv = *(const float4*)&ptb[q * PADP + p0];
                const float fxa[4] = {fx.x, fx.y, fx.z, fx.w};
                const float pva[4] = {pv.x, pv.y, pv.z, pv.w};
                #pragma unroll
                for (int i = 0; i < 4; i++)
                    #pragma unroll
                    for (int pp = 0; pp < 4; pp++)
                        acc[i][pp] = fmaf(fxa[i], pva[pp], acc[i][pp]);
            }
            #pragma unroll
            for (int pp = 0; pp < 4; pp++) {
                float4 o = make_float4(acc[0][pp], acc[1][pp], acc[2][pp], acc[3][pp]);
                *(float4*)&tts[(p0 + pp) * PT + wl0] = o;
            }
        }
        __syncwarp();

        // barrier before first global reduction: all warps' zeros must be visible
        if (c == 0) {
            if (lane == 0) {
                unsigned v;
                do {
                    asm volatile("ld.acquire.gpu.global.u32 %0, [%1];"
                                 : "=r"(v) : "l"(&arrive_g) : "memory");
                } while (v < tgt);
            }
            __syncwarp();
        }

        // stage 2: 42 tasks (hlg 6 x wlq 7), <=2 per lane
        float* cbase = base0 + (size_t)c * (IMG * IMG);
        #pragma unroll
        for (int rep = 0; rep < 2; rep++) {
            const int t = lane + rep * 32;
            if (t < 42) {
                const int wlq = t % 7;
                const int hlg = t / 7;
                const int wl0 = wlq * 4;
                const int hl0 = hlg * 4;

                float acc[4][4] = {};   // [hl][wl]
                #pragma unroll
                for (int p = 0; p < PSZ; p++) {
                    const float4 tv = *(const float4*)&tts[p * PT + wl0];
                    const float4 fy = *(const float4*)&fys[p * PFY + hl0];
                    const float fya[4] = {fy.x, fy.y, fy.z, fy.w};
                    const float tva[4] = {tv.x, tv.y, tv.z, tv.w};
                    #pragma unroll
                    for (int i = 0; i < 4; i++)
                        #pragma unroll
                        for (int k = 0; k < 4; k++)
                            acc[i][k] = fmaf(fya[i], tva[k], acc[i][k]);
                }

                const int wb = w0x + wl0;
                const int hb = w0y + hl0;
                const bool wok = (wb >= 0) && (wb + 3 < IMG);
                #pragma unroll
                for (int i = 0; i < 4; i++) {
                    const int h = hb + i;
                    if (h < 0 || h >= IMG) continue;
                    float* row = cbase + (size_t)h * IMG;
                    if (wok) {
                        asm volatile("red.global.add.v4.f32 [%0], {%1, %2, %3, %4};"
                                     :: "l"(row + wb), "f"(acc[i][0]), "f"(acc[i][1]),
                                        "f"(acc[i][2]), "f"(acc[i][3])
                                     : "memory");
                    } else {
                        #pragma unroll
                        for (int k = 0; k < 4; k++) {
                            const int ww = wb + k;
                            if (ww >= 0 && ww < IMG) atomicAdd(row + ww, acc[i][k]);
                        }
                    }
                }
            }
        }
        __syncwarp();   // tt reused next channel
    }
}

extern "C" void kernel_launch(void* const* d_in, const int* in_sizes, int n_in,
                              void* d_out, int out_size) {
    const float* brushes = (const float*)d_in[0];   // [32,64,2]
    const float* patches = (const float*)d_in[1];   // [32,64,3,16,16]
    float* out = (float*)d_out;                     // [32,3,256,256]

    brush_kernel<<<GRID, 128, WPC * SLOT_F * sizeof(float)>>>(
        brushes, patches, out);
}

// round 12
// speedup vs baseline: 1.0634x; 1.0634x over previous
#include <cuda_runtime.h>
#include <math.h>

#define IMG    256
#define PSZ    16
#define PAD    8
#define NBR    64
#define CH     3
#define INV2S2 12.5f
#define EPSV   1e-7f
#define PADP   20      // patchT row pitch [c][q][p]
#define PFX    28      // FxT row pitch   [q][wl]
#define PFY    24      // FyT row pitch   [p][hl]
#define PT     28      // tT row pitch    [c][p][wl]
#define NBRUSH 2048
#define SLOTS  4
#define GRID   (NBRUSH / SLOTS)   // 512

// dynamic smem layout (floats)
#define SZ_PATCH (CH * PSZ * PADP)   // 960
#define SZ_FX    (PSZ * PFX)         // 448
#define SZ_FY    (PSZ * PFY)         // 384
#define SZ_TT    (CH * PSZ * PT)     // 1344
#define OFF_FX   (SLOTS * SZ_PATCH)
#define OFF_FY   (OFF_FX + SLOTS * SZ_FX)
#define OFF_TT   (OFF_FY + SLOTS * SZ_FY)
#define DYN_FLOATS (OFF_TT + SLOTS * SZ_TT)     // 12544 -> 50176 B

__device__ unsigned int arrive_g;   // monotonic ticket counter (graph-replay safe)

__global__ __launch_bounds__(256) void brush_scatter_kernel(
    const float* __restrict__ brushes,   // [B, N, 2]
    const float* __restrict__ patches,   // [B, N, 3, 16, 16]
    float* __restrict__ out)             // [B, 3, 256, 256]
{
    extern __shared__ __align__(16) float dyn_s[];
    float* patchT_s = dyn_s;                 // [slot][960]
    float* FxT_s    = dyn_s + OFF_FX;        // [slot][448]
    float* FyT_s    = dyn_s + OFF_FY;        // [slot][384]
    float* tT_s     = dyn_s + OFF_TT;        // [slot][1344]

    __shared__ float e_s[SLOTS][2][8];
    __shared__ float rden_s[SLOTS][2][16];
    __shared__ int   t0_s[SLOTS][2];
    __shared__ int   w0_s[SLOTS][2];
    __shared__ unsigned int target_s;

    const int bn0 = blockIdx.x * SLOTS;
    const int b   = bn0 >> 6;
    const int tid = threadIdx.x;

    // ---- phase 0: zero this CTA's 3072-float4 slice; arrive on ticket ----
    {
        float4* out4 = (float4*)out + (size_t)blockIdx.x * 3072 + tid;
        const float4 z = make_float4(0.f, 0.f, 0.f, 0.f);
        #pragma unroll
        for (int k = 0; k < 12; k++) out4[k * 256] = z;
    }
    __threadfence();            // release: zeros visible before arrival
    if (tid == 0) {
        const unsigned ticket = atomicAdd(&arrive_g, 1u);
        target_s = (ticket / GRID + 1u) * GRID;
    }

    // ---- phase A (merged): warps 0-3 tables+filters (slot = warp); warps 4-7 patches ----
    if (tid < 128) {
        const int sw   = tid >> 5;           // slot
        const int lane = tid & 31;
        const float gx = brushes[(bn0 + sw) * 2 + 0] * (float)IMG;
        const float gy = brushes[(bn0 + sw) * 2 + 1] * (float)IMG;
        const int flx = (int)floorf(gx), fly = (int)floorf(gy);
        const int t0x = flx - 10,        t0y = fly - 10;
        const int w0x = (flx - 11) & ~3, w0y = fly - 11;
        if (lane == 0) {
            t0_s[sw][0] = t0x;  t0_s[sw][1] = t0y;
            w0_s[sw][0] = w0x;  w0_s[sw][1] = w0y;
        }
        if (lane < 16) {
            const int ax = lane >> 3;
            const int k  = lane & 7;
            const float g  = ax ? gy : gx;
            const int   t0 = ax ? t0y : t0x;
            const float d  = (float)(t0 + k) - (g - 7.5f);
            e_s[sw][ax][k] = __expf(-d * d * INV2S2);
        }
        __syncwarp();
        {   // reciprocal denominators: ax = lane>>4, q = lane&15
            const int ax = lane >> 4;
            const int q  = lane & 15;
            const int t0 = ax ? t0y : t0x;
            int klo = -PAD - q - t0;            if (klo < 0) klo = 0;
            int khi = (IMG + PAD - 1) - q - t0; if (khi > 7) khi = 7;
            float s = 0.f;
            #pragma unroll
            for (int kk = 0; kk < 8; kk++)
                if (kk >= klo && kk <= khi) s += e_s[sw][ax][kk];
            s += EPSV;
            rden_s[sw][ax][q] = (ax == 0) ? 1.f / (s * (float)NBR) : 1.f / s;
        }
        __syncwarp();
        // filter fill for slot sw (warp-local)
        float* fxb = FxT_s + sw * SZ_FX;
        float* fyb = FyT_s + sw * SZ_FY;
        #pragma unroll
        for (int j = 0; j < 14; j++) {       // fx: 448 entries
            const int i  = lane + j * 32;
            const int q  = i / PFX;
            const int wl = i - q * PFX;
            const int ww = w0x + wl;
            const int idx = ww - q - t0x;
            float val = 0.f;
            if (ww >= 0 && ww < IMG && (unsigned)idx < 8u)
                val = e_s[sw][0][idx] * rden_s[sw][0][q];
            fxb[i] = val;
        }
        #pragma unroll
        for (int j = 0; j < 12; j++) {       // fy: 384 entries
            const int i  = lane + j * 32;
            const int p  = i / PFY;
            const int hl = i - p * PFY;
            const int hh = w0y + hl;
            const int idx = hh - p - t0y;
            float val = 0.f;
            if (hh >= 0 && hh < IMG && (unsigned)idx < 8u)
                val = e_s[sw][1][idx] * rden_s[sw][1][p];
            fyb[i] = val;
        }
    } else {
        // patch transpose: 768 float4 loads -> lane-consecutive scalar stores
        const float4* pbase4 = (const float4*)(patches + (size_t)bn0 * (CH * PSZ * PSZ));
        const int t = tid - 128;
        #pragma unroll
        for (int it = 0; it < 6; it++) {
            const int i = t + it * 128;          // [0, 768)
            const int slot = i / 192;
            const int rem  = i - slot * 192;
            const int qg   = rem / 48;
            const int r2   = rem - qg * 48;
            const int c    = r2 >> 4;
            const int p    = r2 & 15;
            const float4 v = pbase4[slot * 192 + (c * PSZ + p) * 4 + qg];
            float* dst = patchT_s + slot * SZ_PATCH + (c * PSZ + qg * 4) * PADP + p;
            dst[0 * PADP] = v.x;
            dst[1 * PADP] = v.y;
            dst[2 * PADP] = v.z;
            dst[3 * PADP] = v.w;
        }
    }
    __syncthreads();

    // ---- stage 1: tT[c][p][wl] = sum_q FxT[q][wl] * patchT[c][q][p] ----
    for (int t = tid; t < SLOTS * 84; t += 256) {
        const int wlq = t % 7;
        int u = t / 7;
        const int pg = u & 3;  u >>= 2;
        const int c  = u % 3;
        const int slot = u / 3;
        const int p0  = pg * 4;
        const int wl0 = wlq * 4;
        const float* fxb = FxT_s + slot * SZ_FX;
        const float* ptb = patchT_s + slot * SZ_PATCH;

        float acc[4][4] = {};
        #pragma unroll
        for (int q = 0; q < PSZ; q++) {
            const float4 fx = *(const float4*)&fxb[q * PFX + wl0];
            const float4 pv = *(const float4*)&ptb[(c * PSZ + q) * PADP + p0];
            const float fxa[4] = {fx.x, fx.y, fx.z, fx.w};
            const float pva[4] = {pv.x, pv.y, pv.z, pv.w};
            #pragma unroll
            for (int i = 0; i < 4; i++)
                #pragma unroll
                for (int pp = 0; pp < 4; pp++)
                    acc[i][pp] = fmaf(fxa[i], pva[pp], acc[i][pp]);
        }
        float* ttb = tT_s + slot * SZ_TT;
        #pragma unroll
        for (int pp = 0; pp < 4; pp++) {
            float4 o = make_float4(acc[0][pp], acc[1][pp], acc[2][pp], acc[3][pp]);
            *(float4*)&ttb[(c * PSZ + p0 + pp) * PT + wl0] = o;
        }
    }

    // ---- grid barrier: every CTA's zero phase completed (long ago) ----
    if (tid == 0) {
        const unsigned tgt = target_s;
        unsigned v;
        do {
            asm volatile("ld.acquire.gpu.global.u32 %0, [%1];"
                         : "=r"(v) : "l"(&arrive_g) : "memory");
            if (v >= tgt) break;
            __nanosleep(64);
        } while (true);
    }
    __syncthreads();   // also covers stage1 -> stage2 smem dependency

    // ---- stage 2: 4x4 output blocks, vectorized global reduction ----
    for (int t = tid; t < SLOTS * 126; t += 256) {
        const int wlq = t % 7;
        int u = t / 7;
        const int hlg = u % 6;  u /= 6;
        const int c   = u % 3;
        const int slot = u / 3;
        const int wl0 = wlq * 4;
        const int hl0 = hlg * 4;
        const float* ttb = tT_s + slot * SZ_TT;
        const float* fyb = FyT_s + slot * SZ_FY;

        float acc[4][4] = {};
        #pragma unroll
        for (int p = 0; p < PSZ; p++) {
            const float4 tv = *(const float4*)&ttb[(c * PSZ + p) * PT + wl0];
            const float4 fy = *(const float4*)&fyb[p * PFY + hl0];
            const float fya[4] = {fy.x, fy.y, fy.z, fy.w};
            const float tva[4] = {tv.x, tv.y, tv.z, tv.w};
            #pragma unroll
            for (int i = 0; i < 4; i++)
                #pragma unroll
                for (int k = 0; k < 4; k++)
                    acc[i][k] = fmaf(fya[i], tva[k], acc[i][k]);
        }

        const int wb = w0_s[slot][0] + wl0;
        const int hb = w0_s[slot][1] + hl0;
        float* base = out + ((size_t)b * CH + c) * (IMG * IMG);
        const bool wok = (wb >= 0) && (wb + 3 < IMG);
        #pragma unroll
        for (int i = 0; i < 4; i++) {
            const int h = hb + i;
            if (h < 0 || h >= IMG) continue;
            float* row = base + (size_t)h * IMG;
            if (wok) {
                asm volatile("red.global.add.v4.f32 [%0], {%1, %2, %3, %4};"
                             :: "l"(row + wb), "f"(acc[i][0]), "f"(acc[i][1]),
                                "f"(acc[i][2]), "f"(acc[i][3])
                             : "memory");
            } else {
                #pragma unroll
                for (int k = 0; k < 4; k++) {
                    const int w = wb + k;
                    if (w >= 0 && w < IMG) atomicAdd(row + w, acc[i][k]);
                }
            }
        }
    }
}

extern "C" void kernel_launch(void* const* d_in, const int* in_sizes, int n_in,
                              void* d_out, int out_size) {
    const float* brushes = (const float*)d_in[0];   // [32,64,2]
    const float* patches = (const float*)d_in[1];   // [32,64,3,16,16]
    float* out = (float*)d_out;                     // [32,3,256,256]

    static bool attr_set = false;
    if (!attr_set) {
        cudaFuncSetAttribute(brush_scatter_kernel,
                             cudaFuncAttributeMaxDynamicSharedMemorySize,
                             DYN_FLOATS * (int)sizeof(float));
        attr_set = true;
    }

    brush_scatter_kernel<<<GRID, 256, DYN_FLOATS * sizeof(float)>>>(
        brushes, patches, out);
}

// round 13
// speedup vs baseline: 1.1644x; 1.0950x over previous
#include <cuda_runtime.h>
#include <math.h>

#define IMG    256
#define PSZ    16
#define PAD    8
#define NBR    64
#define CH     3
#define INV2S2 12.5f
#define EPSV   1e-7f
#define PADP   20      // patchT row pitch [c][q][p]
#define PFX    28      // FxT row pitch   [q][wl]
#define PFY    24      // FyT row pitch   [p][hl]
#define PT     28      // tT row pitch    [c][p][wl]
#define NBRUSH 2048
#define SLOTS  4
#define GRID   (NBRUSH / SLOTS)   // 512

// dynamic smem layout (floats)
#define SZ_PATCH (CH * PSZ * PADP)   // 960
#define SZ_FX    (PSZ * PFX)         // 448
#define SZ_FY    (PSZ * PFY)         // 384
#define SZ_TT    (CH * PSZ * PT)     // 1344
#define OFF_FX   (SLOTS * SZ_PATCH)
#define OFF_FY   (OFF_FX + SLOTS * SZ_FX)
#define OFF_TT   (OFF_FY + SLOTS * SZ_FY)
#define DYN_FLOATS (OFF_TT + SLOTS * SZ_TT)     // 12544 -> 50176 B

__global__ __launch_bounds__(256) void brush_scatter_kernel(
    const float* __restrict__ brushes,   // [B, N, 2]
    const float* __restrict__ patches,   // [B, N, 3, 16, 16]
    float* __restrict__ out)             // [B, 3, 256, 256]
{
    extern __shared__ __align__(16) float dyn_s[];
    float* patchT_s = dyn_s;                 // [slot][960]
    float* FxT_s    = dyn_s + OFF_FX;        // [slot][448]
    float* FyT_s    = dyn_s + OFF_FY;        // [slot][384]
    float* tT_s     = dyn_s + OFF_TT;        // [slot][1344]

    __shared__ float e_s[SLOTS][2][8];
    __shared__ float rden_s[SLOTS][2][16];
    __shared__ int   t0_s[SLOTS][2];
    __shared__ int   w0_s[SLOTS][2];

    const int bn0 = blockIdx.x * SLOTS;
    const int b   = bn0 >> 6;
    const int tid = threadIdx.x;

    // ---- phase A: warps 0-1 exp tables + denoms; warps 2-7 patch loads ----
    if (tid < 64) {
        const int slot = tid >> 4;
        const int ax   = (tid >> 3) & 1;
        const int k    = tid & 7;
        const float g  = brushes[(bn0 + slot) * 2 + ax] * (float)IMG;
        const int  fl  = (int)floorf(g);
        const int  t0  = fl - 10;
        const float d  = (float)(t0 + k) - (g - 7.5f);
        e_s[slot][ax][k] = __expf(-d * d * INV2S2);
        if (k == 0) {
            t0_s[slot][ax] = t0;
            w0_s[slot][ax] = (ax == 0) ? ((fl - 11) & ~3) : (fl - 11);
        }
        __syncwarp();
        #pragma unroll
        for (int h = 0; h < 2; h++) {
            const int q = k + h * 8;
            int klo = -PAD - q - t0;            if (klo < 0) klo = 0;
            int khi = (IMG + PAD - 1) - q - t0; if (khi > 7) khi = 7;
            float s = 0.f;
            #pragma unroll
            for (int kk = 0; kk < 8; kk++)
                if (kk >= klo && kk <= khi) s += e_s[slot][ax][kk];
            s += EPSV;
            rden_s[slot][ax][q] = (ax == 0) ? 1.f / (s * (float)NBR) : 1.f / s;
        }
    } else {
        const float* pbase = patches + (size_t)bn0 * (CH * PSZ * PSZ);
        const int t = tid - 64;
        #pragma unroll
        for (int it = 0; it < 16; it++) {
            const int i = t + it * 192;          // 3072 elems total
            const int slot = i / 768;
            const int r = i - slot * 768;
            const int c = r >> 8;
            const int p = (r >> 4) & 15;
            const int q = r & 15;
            patchT_s[slot * SZ_PATCH + (c * PSZ + q) * PADP + p] = pbase[i];
        }
    }
    __syncthreads();

    // ---- phase B: fill FxT[q][wl] + FyT[p][hl] via lookups (4*832 entries) ----
    #pragma unroll
    for (int it = 0; it < 13; it++) {
        const int i = tid + it * 256;
        if (i >= SLOTS * 832) break;
        const int slot = i / 832;
        const int r    = i - slot * 832;
        if (r < PSZ * PFX) {
            const int q  = r / PFX;
            const int wl = r - q * PFX;
            const int w  = w0_s[slot][0] + wl;
            const int idx = w - q - t0_s[slot][0];
            float val = 0.f;
            if (w >= 0 && w < IMG && (unsigned)idx < 8u)
                val = e_s[slot][0][idx] * rden_s[slot][0][q];
            FxT_s[slot * SZ_FX + r] = val;
        } else {
            const int rr = r - PSZ * PFX;
            const int p  = rr / PFY;
            const int hl = rr - p * PFY;
            const int h  = w0_s[slot][1] + hl;
            const int idx = h - p - t0_s[slot][1];
            float val = 0.f;
            if (h >= 0 && h < IMG && (unsigned)idx < 8u)
                val = e_s[slot][1][idx] * rden_s[slot][1][p];
            FyT_s[slot * SZ_FY + rr] = val;
        }
    }
    __syncthreads();

    // ---- stage 1: tT[c][p][wl] = sum_q FxT[q][wl] * patchT[c][q][p] ----
    // task = (slot, c, pg{0,1}, wlq{0..6}): 168 tasks, 8p x 4wl block
    if (tid < SLOTS * 42) {
        const int wlq = tid % 7;
        int u = tid / 7;
        const int pg = u & 1;  u >>= 1;
        const int c  = u % 3;
        const int slot = u / 3;
        const int p0  = pg * 8;
        const int wl0 = wlq * 4;
        const float* fxb = FxT_s + slot * SZ_FX;
        const float* ptb = patchT_s + slot * SZ_PATCH;

        float acc[4][8] = {};   // [wl][p]
        #pragma unroll
        for (int q = 0; q < PSZ; q++) {
            const float4 fx  = *(const float4*)&fxb[q * PFX + wl0];
            const float4 pv0 = *(const float4*)&ptb[(c * PSZ + q) * PADP + p0];
            const float4 pv1 = *(const float4*)&ptb[(c * PSZ + q) * PADP + p0 + 4];
            const float fxa[4] = {fx.x, fx.y, fx.z, fx.w};
            const float pva[8] = {pv0.x, pv0.y, pv0.z, pv0.w,
                                  pv1.x, pv1.y, pv1.z, pv1.w};
            #pragma unroll
            for (int i = 0; i < 4; i++)
                #pragma unroll
                for (int pp = 0; pp < 8; pp++)
                    acc[i][pp] = fmaf(fxa[i], pva[pp], acc[i][pp]);
        }
        float* ttb = tT_s + slot * SZ_TT;
        #pragma unroll
        for (int pp = 0; pp < 8; pp++) {
            float4 o = make_float4(acc[0][pp], acc[1][pp], acc[2][pp], acc[3][pp]);
            *(float4*)&ttb[(c * PSZ + p0 + pp) * PT + wl0] = o;
        }
    }
    __syncthreads();

    // ---- stage 2: task = (slot, c, hg{0,1,2}, wlq{0..6}): 252 tasks, 8h x 4w ----
    if (tid < SLOTS * 63) {
        const int wlq = tid % 7;
        int u = tid / 7;
        const int hg = u % 3;  u /= 3;
        const int c  = u % 3;
        const int slot = u / 3;
        const int wl0 = wlq * 4;
        const int hl0 = hg * 8;
        const float* ttb = tT_s + slot * SZ_TT;
        const float* fyb = FyT_s + slot * SZ_FY;

        float acc[8][4] = {};   // [hl][wl]
        #pragma unroll
        for (int p = 0; p < PSZ; p++) {
            const float4 tv  = *(const float4*)&ttb[(c * PSZ + p) * PT + wl0];
            const float4 fy0 = *(const float4*)&fyb[p * PFY + hl0];
            const float4 fy1 = *(const float4*)&fyb[p * PFY + hl0 + 4];
            const float fya[8] = {fy0.x, fy0.y, fy0.z, fy0.w,
                                  fy1.x, fy1.y, fy1.z, fy1.w};
            const float tva[4] = {tv.x, tv.y, tv.z, tv.w};
            #pragma unroll
            for (int i = 0; i < 8; i++)
                #pragma unroll
                for (int k = 0; k < 4; k++)
                    acc[i][k] = fmaf(fya[i], tva[k], acc[i][k]);
        }

        const int wb = w0_s[slot][0] + wl0;
        const int hb = w0_s[slot][1] + hl0;
        float* base = out + ((size_t)b * CH + c) * (IMG * IMG);
        const bool wok = (wb >= 0) && (wb + 3 < IMG);
        #pragma unroll
        for (int i = 0; i < 8; i++) {
            const int h = hb + i;
            if (h < 0 || h >= IMG) continue;
            float* row = base + (size_t)h * IMG;
            if (wok) {
                asm volatile("red.global.add.v4.f32 [%0], {%1, %2, %3, %4};"
                             :: "l"(row + wb), "f"(acc[i][0]), "f"(acc[i][1]),
                                "f"(acc[i][2]), "f"(acc[i][3])
                             : "memory");
            } else {
                #pragma unroll
                for (int k = 0; k < 4; k++) {
                    const int w = wb + k;
                    if (w >= 0 && w < IMG) atomicAdd(row + w, acc[i][k]);
                }
            }
        }
    }
}

extern "C" void kernel_launch(void* const* d_in, const int* in_sizes, int n_in,
                              void* d_out, int out_size) {
    const float* brushes = (const float*)d_in[0];   // [32,64,2]
    const float* patches = (const float*)d_in[1];   // [32,64,3,16,16]
    float* out = (float*)d_out;                     // [32,3,256,256]

    static bool attr_set = false;
    if (!attr_set) {
        cudaFuncSetAttribute(brush_scatter_kernel,
                             cudaFuncAttributeMaxDynamicSharedMemorySize,
                             DYN_FLOATS * (int)sizeof(float));
        attr_set = true;
    }

    cudaMemsetAsync(out, 0, (size_t)out_size * sizeof(float), 0);
    brush_scatter_kernel<<<GRID, 256, DYN_FLOATS * sizeof(float)>>>(
        brushes, patches, out);
}